// round 14
// baseline (speedup 1.0000x reference)
#include <cuda_runtime.h>
#include <cstdint>

// ---------------- problem constants ----------------
constexpr int NTOK  = 197;
constexpr int DIMC  = 768;
constexpr int NH    = 12;
constexpr int HDIM  = 64;
constexpr int NB    = 128;
constexpr int MROWS = NB * NTOK;    // 25216
constexpr int NBH   = NB * NH;      // 1536

// ---------------- scratch (device globals) ----------------
__device__ float g_q[(size_t)NBH * NTOK * HDIM];
__device__ float g_k[(size_t)NBH * NTOK * HDIM];
__device__ float g_v[(size_t)NBH * NTOK * HDIM];
__device__ float g_o[(size_t)MROWS * DIMC];      // written TF32-rounded by attention
__device__ float g_rpb[NH * NTOK * NTOK];
__device__ float g_xc[(size_t)MROWS * DIMC];     // tf32-rounded x
__device__ float g_wc[(size_t)3 * DIMC * DIMC];  // tf32-rounded qkv_w
__device__ float g_pwc[(size_t)DIMC * DIMC];     // tf32-rounded proj_w

// ---------------- helpers ----------------
__device__ __forceinline__ float f2tf32(float x) {
    unsigned u;
    asm("cvt.rna.tf32.f32 %0, %1;" : "=r"(u) : "f"(x));
    return __uint_as_float(u);
}

__device__ __forceinline__ void mma_tf32(float c[4], const float a[4], const float b[2]) {
    asm volatile(
        "mma.sync.aligned.m16n8k8.row.col.f32.tf32.tf32.f32 "
        "{%0,%1,%2,%3}, {%4,%5,%6,%7}, {%8,%9}, {%0,%1,%2,%3};"
        : "+f"(c[0]), "+f"(c[1]), "+f"(c[2]), "+f"(c[3])
        : "r"(__float_as_uint(a[0])), "r"(__float_as_uint(a[1])),
          "r"(__float_as_uint(a[2])), "r"(__float_as_uint(a[3])),
          "r"(__float_as_uint(b[0])), "r"(__float_as_uint(b[1])));
}

__device__ __forceinline__ void ldsm_x4(uint32_t addr, float d[4]) {
    uint32_t r0, r1, r2, r3;
    asm volatile("ldmatrix.sync.aligned.m8n8.x4.shared.b16 {%0,%1,%2,%3}, [%4];"
                 : "=r"(r0), "=r"(r1), "=r"(r2), "=r"(r3) : "r"(addr));
    d[0] = __uint_as_float(r0); d[1] = __uint_as_float(r1);
    d[2] = __uint_as_float(r2); d[3] = __uint_as_float(r3);
}

__device__ __forceinline__ uint32_t smem_u32(const void* p) {
    return (uint32_t)__cvta_generic_to_shared(p);
}

__device__ __forceinline__ void cp_async16(uint32_t dst, const void* src) {
    asm volatile("cp.async.cg.shared.global [%0], [%1], 16;"
                 :: "r"(dst), "l"(src) : "memory");
}
__device__ __forceinline__ void cp_commit() {
    asm volatile("cp.async.commit_group;" ::: "memory");
}
__device__ __forceinline__ void cp_wait2() {
    asm volatile("cp.async.wait_group 2;" ::: "memory");
}

// ---------------- prepass: tf32-round all operands (one kernel) -------------
constexpr int CVT_N0 = MROWS * DIMC / 4;          // x       -> g_xc
constexpr int CVT_N1 = 3 * DIMC * DIMC / 4;       // qkv_w   -> g_wc
constexpr int CVT_N2 = DIMC * DIMC / 4;           // proj_w  -> g_pwc
__global__ void cvt_all_k(const float* __restrict__ x,
                          const float* __restrict__ qw,
                          const float* __restrict__ pw)
{
    int i = blockIdx.x * 256 + threadIdx.x;
    const float4* s; float4* d;
    if (i < CVT_N0)                       { s = (const float4*)x  + i;            d = (float4*)g_xc  + i; }
    else if ((i -= CVT_N0) < CVT_N1)      { s = (const float4*)qw + i;            d = (float4*)g_wc  + i; }
    else if ((i -= CVT_N1) < CVT_N2)      { s = (const float4*)pw + i;            d = (float4*)g_pwc + i; }
    else return;
    float4 v = *s;
    *d = make_float4(f2tf32(v.x), f2tf32(v.y), f2tf32(v.z), f2tf32(v.w));
}

// ---------------- rpb gather expansion ----------------
__global__ void rpb_expand_k(const int* __restrict__ rel_idx,
                             const float* __restrict__ table)
{
    int ij = blockIdx.x * 256 + threadIdx.x;
    if (ij >= NTOK * NTOK) return;
    int rel = rel_idx[ij];
    #pragma unroll
    for (int h = 0; h < NH; h++)
        g_rpb[h * NTOK * NTOK + ij] = table[rel * NH + h];
}

// ---------------- TF32 GEMM: 128x128 block, GBK=16, 4-stage cp.async --------
// MODE 0: QKV  [25216,2304] = g_xc @ g_wc^T (+bias, scale, scatter q/k/v)
// MODE 3: proj [25216,768]  = g_o  @ g_pwc^T (+bias)
constexpr int GBM = 128, GBN = 128, GBK = 16, GLD = 20, NSTG = 4;
constexpr int GEMM_SMEM = NSTG * (GBM + GBN) * GLD * 4;   // 81920 B

template<int MODE>
__global__ void __launch_bounds__(128, 2) gemm_tc(const float* __restrict__ P1,
                                                  const float* __restrict__ P2,
                                                  float* __restrict__ C_)
{
    constexpr int Kdim = DIMC;
    constexpr int NKT  = Kdim / GBK;               // 48

    const float* A  = (MODE == 3) ? (const float*)g_o : (const float*)g_xc;
    const float* Bm = (MODE == 3) ? (const float*)g_pwc : (const float*)g_wc;

    const int m0  = blockIdx.y * GBM;
    const int n0  = blockIdx.x * GBN;
    const int tid = threadIdx.x;
    const int w    = tid >> 5, lane = tid & 31;
    const int gid  = lane >> 2, tig = lane & 3;
    const int wm   = (w & 1) * 64;
    const int wn   = (w >> 1) * 64;

    extern __shared__ float smg[];
    float* As = smg;                              // [NSTG][GBM*GLD]
    float* Bs = smg + NSTG * GBM * GLD;           // [NSTG][GBN*GLD]

    const int sr = tid >> 2;            // 0..31
    const int sc = (tid & 3) * 4;

    const float* pa = &A [(size_t)(m0 + sr) * Kdim + sc];
    const float* pb = &Bm[(size_t)(n0 + sr) * Kdim + sc];

    float acc[4][8][4] = {};

    const int lt   = lane >> 3;
    const int li   = lane & 7;
    const int a_row = wm + (lt & 1) * 8 + li;
    const int a_col = (lt >> 1) * 4;
    const int b_row = wn + (lt >> 1) * 8 + li;
    const int b_col = (lt & 1) * 4;

    auto STAGE = [&](int kt_idx, int buf) {
        float* ab = As + buf * GBM * GLD;
        float* bb = Bs + buf * GBN * GLD;
        const int kt = kt_idx * GBK;
        #pragma unroll
        for (int r = 0; r < 4; r++) {
            cp_async16(smem_u32(&ab[(sr + r * 32) * GLD + sc]),
                       pa + (size_t)(r * 32) * Kdim + kt);
            cp_async16(smem_u32(&bb[(sr + r * 32) * GLD + sc]),
                       pb + (size_t)(r * 32) * Kdim + kt);
        }
    };
    auto MMA_ALL = [&](int buf) {
        const float* ab = As + buf * GBM * GLD;
        const float* bb = Bs + buf * GBN * GLD;
        #pragma unroll
        for (int kc = 0; kc < 2; kc++) {
            float af[4][4], bf[8][2];
            #pragma unroll
            for (int mt = 0; mt < 4; mt++) {
                uint32_t ad = smem_u32(&ab[(a_row + mt * 16) * GLD + a_col + kc * 8]);
                ldsm_x4(ad, af[mt]);
            }
            #pragma unroll
            for (int p = 0; p < 4; p++) {
                float t4[4];
                uint32_t ad = smem_u32(&bb[(b_row + p * 16) * GLD + b_col + kc * 8]);
                ldsm_x4(ad, t4);
                bf[p*2  ][0] = t4[0]; bf[p*2  ][1] = t4[1];
                bf[p*2+1][0] = t4[2]; bf[p*2+1][1] = t4[3];
            }
            #pragma unroll
            for (int mt = 0; mt < 4; mt++)
                #pragma unroll
                for (int nt = 0; nt < 8; nt++)
                    mma_tf32(acc[mt][nt], af[mt], bf[nt]);
        }
    };

    // prologue: tiles 0..2 in flight (prefetch distance 3)
    STAGE(0, 0); cp_commit();
    STAGE(1, 1); cp_commit();
    STAGE(2, 2); cp_commit();
    for (int it = 0; it < NKT; it++) {
        cp_wait2();                 // all but last 2 groups done -> tile `it` resident
        __syncthreads();            // every warp finished MMA(it-1) -> buffer (it+3)%4 drained
        if (it + 3 < NKT) STAGE(it + 3, (it + 3) % NSTG);
        cp_commit();                // empty group keeps pending-count semantics
        MMA_ALL(it % NSTG);
    }

    #pragma unroll
    for (int mt = 0; mt < 4; mt++) {
        #pragma unroll
        for (int nt = 0; nt < 8; nt++) {
            #pragma unroll
            for (int e = 0; e < 4; e++) {
                int gm = m0 + wm + mt * 16 + gid + ((e >> 1) ? 8 : 0);
                int gn = n0 + wn + nt * 8 + tig * 2 + (e & 1);
                float v = acc[mt][nt][e];
                if (MODE == 0) {
                    int b = gm / NTOK, n = gm % NTOK;
                    int s = gn / DIMC, r = gn % DIMC;
                    int h = r / HDIM,  d = r % HDIM;
                    size_t o = ((size_t)(b * NH + h) * NTOK + n) * HDIM + d;
                    if (s == 0)      g_q[o] = (v + P1[r]) * 0.125f;
                    else if (s == 1) g_k[o] = v;
                    else             g_v[o] = v + P2[r];
                } else {
                    C_[(size_t)gm * DIMC + gn] = v + P1[gn];
                }
            }
        }
    }
}

// ---------------- fused attention: 2 CTAs per (b,h), 4 warps each ------------
constexpr int NP        = 208;
constexpr int KS_STRIDE = 68;
constexpr int VT_STRIDE = 212;
constexpr int ATT_SMEM  = (NP * KS_STRIDE + HDIM * VT_STRIDE) * 4;

__global__ void __launch_bounds__(128, 2) attn_fused_k()
{
    const int z    = blockIdx.x >> 1;
    const int half = blockIdx.x & 1;
    const int h = z % NH;
    const int b = z / NH;
    const float* q   = g_q + (size_t)z * NTOK * HDIM;
    const float* kk  = g_k + (size_t)z * NTOK * HDIM;
    const float* vv  = g_v + (size_t)z * NTOK * HDIM;
    const float* rpb = g_rpb + (size_t)h * NTOK * NTOK;

    extern __shared__ float sm[];
    float* ks = sm;
    float* vT = sm + NP * KS_STRIDE;

    const int tid = threadIdx.x;

    for (int idx = tid; idx < NP * 16; idx += 128) {
        int tok = idx >> 4, d4 = (idx & 15) * 4;
        float4 val = make_float4(0.f, 0.f, 0.f, 0.f);
        if (tok < NTOK) val = *(const float4*)&kk[tok * HDIM + d4];
        ks[tok * KS_STRIDE + d4 + 0] = f2tf32(val.x);
        ks[tok * KS_STRIDE + d4 + 1] = f2tf32(val.y);
        ks[tok * KS_STRIDE + d4 + 2] = f2tf32(val.z);
        ks[tok * KS_STRIDE + d4 + 3] = f2tf32(val.w);
    }
    for (int idx = tid; idx < NP * 16; idx += 128) {
        int tok = idx >> 4, d4 = (idx & 15) * 4;
        float4 val = make_float4(0.f, 0.f, 0.f, 0.f);
        if (tok < NTOK) val = *(const float4*)&vv[tok * HDIM + d4];
        vT[(d4 + 0) * VT_STRIDE + tok] = f2tf32(val.x);
        vT[(d4 + 1) * VT_STRIDE + tok] = f2tf32(val.y);
        vT[(d4 + 2) * VT_STRIDE + tok] = f2tf32(val.z);
        vT[(d4 + 3) * VT_STRIDE + tok] = f2tf32(val.w);
    }
    __syncthreads();

    const int w = tid >> 5, lane = tid & 31, gid = lane >> 2, tig = lane & 3;
    const int lt = lane >> 3, li = lane & 7;
    const int bs_row = (lt >> 1) * 8 + li;
    const int bs_col = (lt & 1) * 4;

    for (int r = 0; r < 2; r++) {
        const int t = half + 2 * (w + 4 * r);
        if (t >= 13) break;
        const int m0 = t * 16;
        const int mA = m0 + gid;
        const int mB = m0 + gid + 8;

        float aq[8][4];
        #pragma unroll
        for (int kt = 0; kt < 8; kt++) {
            int c0 = kt * 8 + tig, c1 = c0 + 4;
            aq[kt][0] = (mA < NTOK) ? f2tf32(q[mA * HDIM + c0]) : 0.f;
            aq[kt][1] = (mB < NTOK) ? f2tf32(q[mB * HDIM + c0]) : 0.f;
            aq[kt][2] = (mA < NTOK) ? f2tf32(q[mA * HDIM + c1]) : 0.f;
            aq[kt][3] = (mB < NTOK) ? f2tf32(q[mB * HDIM + c1]) : 0.f;
        }

        float acc[26][4];
        #pragma unroll
        for (int nt = 0; nt < 26; nt++)
            acc[nt][0] = acc[nt][1] = acc[nt][2] = acc[nt][3] = 0.f;
        #pragma unroll
        for (int np = 0; np < 13; np++) {
            #pragma unroll
            for (int kt = 0; kt < 8; kt++) {
                float t4[4];
                uint32_t ad = smem_u32(&ks[(np * 16 + bs_row) * KS_STRIDE + bs_col + kt * 8]);
                ldsm_x4(ad, t4);
                float bk0[2] = { t4[0], t4[1] };
                float bk1[2] = { t4[2], t4[3] };
                mma_tf32(acc[np * 2    ], aq[kt], bk0);
                mma_tf32(acc[np * 2 + 1], aq[kt], bk1);
            }
        }

        const float* rA = rpb + (size_t)min(mA, NTOK - 1) * NTOK;
        const float* rB = rpb + (size_t)min(mB, NTOK - 1) * NTOK;
        float mx0 = -1e30f, mx1 = -1e30f;
        #pragma unroll
        for (int nt = 0; nt < 26; nt++) {
            int c0 = nt * 8 + tig * 2, c1 = c0 + 1;
            acc[nt][0] = (c0 < NTOK) ? acc[nt][0] + rA[c0] : -1e30f;
            acc[nt][1] = (c1 < NTOK) ? acc[nt][1] + rA[c1] : -1e30f;
            acc[nt][2] = (c0 < NTOK) ? acc[nt][2] + rB[c0] : -1e30f;
            acc[nt][3] = (c1 < NTOK) ? acc[nt][3] + rB[c1] : -1e30f;
            mx0 = fmaxf(mx0, fmaxf(acc[nt][0], acc[nt][1]));
            mx1 = fmaxf(mx1, fmaxf(acc[nt][2], acc[nt][3]));
        }
        #pragma unroll
        for (int o = 1; o <= 2; o <<= 1) {
            mx0 = fmaxf(mx0, __shfl_xor_sync(~0u, mx0, o));
            mx1 = fmaxf(mx1, __shfl_xor_sync(~0u, mx1, o));
        }
        float s0 = 0.f, s1 = 0.f;
        #pragma unroll
        for (int nt = 0; nt < 26; nt++) {
            acc[nt][0] = __expf(acc[nt][0] - mx0);
            acc[nt][1] = __expf(acc[nt][1] - mx0);
            acc[nt][2] = __expf(acc[nt][2] - mx1);
            acc[nt][3] = __expf(acc[nt][3] - mx1);
            s0 += acc[nt][0] + acc[nt][1];
            s1 += acc[nt][2] + acc[nt][3];
        }
        #pragma unroll
        for (int o = 1; o <= 2; o <<= 1) {
            s0 += __shfl_xor_sync(~0u, s0, o);
            s1 += __shfl_xor_sync(~0u, s1, o);
        }
        const float i0 = 1.f / s0, i1 = 1.f / s1;
        #pragma unroll
        for (int nt = 0; nt < 26; nt++) {
            acc[nt][0] *= i0; acc[nt][1] *= i0;
            acc[nt][2] *= i1; acc[nt][3] *= i1;
        }

        float acc2[8][4];
        #pragma unroll
        for (int nt = 0; nt < 8; nt++)
            acc2[nt][0] = acc2[nt][1] = acc2[nt][2] = acc2[nt][3] = 0.f;

        const int src0 = (lane & ~3) | (tig >> 1);
        const int src1 = src0 + 2;
        const bool odd = tig & 1;
        #pragma unroll
        for (int kt = 0; kt < 26; kt++) {
            float v00 = __shfl_sync(~0u, acc[kt][0], src0);
            float v01 = __shfl_sync(~0u, acc[kt][1], src0);
            float v02 = __shfl_sync(~0u, acc[kt][2], src0);
            float v03 = __shfl_sync(~0u, acc[kt][3], src0);
            float w00 = __shfl_sync(~0u, acc[kt][0], src1);
            float w01 = __shfl_sync(~0u, acc[kt][1], src1);
            float w02 = __shfl_sync(~0u, acc[kt][2], src1);
            float w03 = __shfl_sync(~0u, acc[kt][3], src1);
            float aP[4];
            aP[0] = f2tf32(odd ? v01 : v00);
            aP[1] = f2tf32(odd ? v03 : v02);
            aP[2] = f2tf32(odd ? w01 : w00);
            aP[3] = f2tf32(odd ? w03 : w02);
            #pragma unroll
            for (int np = 0; np < 4; np++) {
                float t4[4];
                uint32_t ad = smem_u32(&vT[(np * 16 + bs_row) * VT_STRIDE + bs_col + kt * 8]);
                ldsm_x4(ad, t4);
                float bv0[2] = { t4[0], t4[1] };
                float bv1[2] = { t4[2], t4[3] };
                mma_tf32(acc2[np * 2    ], aP, bv0);
                mma_tf32(acc2[np * 2 + 1], aP, bv1);
            }
        }

        #pragma unroll
        for (int nt = 0; nt < 8; nt++) {
            int d0 = nt * 8 + tig * 2;
            if (mA < NTOK) {
                float* o = &g_o[((size_t)(b * NTOK + mA)) * DIMC + h * HDIM + d0];
                o[0] = f2tf32(acc2[nt][0]); o[1] = f2tf32(acc2[nt][1]);
            }
            if (mB < NTOK) {
                float* o = &g_o[((size_t)(b * NTOK + mB)) * DIMC + h * HDIM + d0];
                o[0] = f2tf32(acc2[nt][2]); o[1] = f2tf32(acc2[nt][3]);
            }
        }
    }
}

// ---------------- launch ----------------
extern "C" void kernel_launch(void* const* d_in, const int* in_sizes, int n_in,
                              void* d_out, int out_size)
{
    const float* x = nullptr; const float* qkv_w = nullptr;
    const float* proj_w = nullptr; const float* rpb_table = nullptr;
    const int*   rel_idx = nullptr;
    const float* bias768[3] = {nullptr, nullptr, nullptr};
    int nbias = 0;
    for (int i = 0; i < n_in; i++) {
        switch (in_sizes[i]) {
            case MROWS * DIMC:    x         = (const float*)d_in[i]; break;
            case 3 * DIMC * DIMC: qkv_w     = (const float*)d_in[i]; break;
            case DIMC * DIMC:     proj_w    = (const float*)d_in[i]; break;
            case NTOK * NTOK:     rel_idx   = (const int*)d_in[i];   break;
            case 732 * NH:        rpb_table = (const float*)d_in[i]; break;
            case DIMC:            if (nbias < 3) bias768[nbias++] = (const float*)d_in[i]; break;
            default: break;
        }
    }
    const float* q_bias = bias768[0];
    const float* v_bias = bias768[1];
    const float* proj_b = bias768[2];
    float* out = (float*)d_out;

    cudaFuncSetAttribute(attn_fused_k, cudaFuncAttributeMaxDynamicSharedMemorySize, ATT_SMEM);
    cudaFuncSetAttribute(gemm_tc<0>, cudaFuncAttributeMaxDynamicSharedMemorySize, GEMM_SMEM);
    cudaFuncSetAttribute(gemm_tc<3>, cudaFuncAttributeMaxDynamicSharedMemorySize, GEMM_SMEM);

    // 0) prepass: tf32-round operands; expand rpb
    constexpr int CVT_TOT = CVT_N0 + CVT_N1 + CVT_N2;
    cvt_all_k<<<(CVT_TOT + 255) / 256, 256>>>(x, qkv_w, proj_w);
    rpb_expand_k<<<(NTOK * NTOK + 255) / 256, 256>>>(rel_idx, rpb_table);

    // 1) QKV projection: grid (2304/128, 25216/128)
    gemm_tc<0><<<dim3(18, 197), 128, GEMM_SMEM>>>(q_bias, v_bias, nullptr);

    // 2) fused attention: 2 CTAs per (b,h)
    attn_fused_k<<<NBH * 2, 128, ATT_SMEM>>>();

    // 3) final projection + bias: grid (768/128, 197)
    gemm_tc<3><<<dim3(6, 197), 128, GEMM_SMEM>>>(proj_b, nullptr, out);
}

// round 15
// speedup vs baseline: 1.5025x; 1.5025x over previous
#include <cuda_runtime.h>
#include <cstdint>

// ---------------- problem constants ----------------
constexpr int NTOK  = 197;
constexpr int DIMC  = 768;
constexpr int NH    = 12;
constexpr int HDIM  = 64;
constexpr int NB    = 128;
constexpr int MROWS = NB * NTOK;    // 25216
constexpr int NBH   = NB * NH;      // 1536

// ---------------- scratch (device globals) ----------------
__device__ float g_q[(size_t)NBH * NTOK * HDIM];
__device__ float g_k[(size_t)NBH * NTOK * HDIM];
__device__ float g_v[(size_t)NBH * NTOK * HDIM];
__device__ float g_o[(size_t)MROWS * DIMC];      // written TF32-rounded by attention
__device__ float g_rpb[NH * NTOK * NTOK];
__device__ float g_xc[(size_t)MROWS * DIMC];     // tf32-rounded x
__device__ float g_wc[(size_t)3 * DIMC * DIMC];  // tf32-rounded qkv_w
__device__ float g_pwc[(size_t)DIMC * DIMC];     // tf32-rounded proj_w

// ---------------- helpers ----------------
__device__ __forceinline__ float f2tf32(float x) {
    unsigned u;
    asm("cvt.rna.tf32.f32 %0, %1;" : "=r"(u) : "f"(x));
    return __uint_as_float(u);
}

__device__ __forceinline__ void mma_tf32(float c[4], const float a[4], const float b[2]) {
    asm volatile(
        "mma.sync.aligned.m16n8k8.row.col.f32.tf32.tf32.f32 "
        "{%0,%1,%2,%3}, {%4,%5,%6,%7}, {%8,%9}, {%0,%1,%2,%3};"
        : "+f"(c[0]), "+f"(c[1]), "+f"(c[2]), "+f"(c[3])
        : "r"(__float_as_uint(a[0])), "r"(__float_as_uint(a[1])),
          "r"(__float_as_uint(a[2])), "r"(__float_as_uint(a[3])),
          "r"(__float_as_uint(b[0])), "r"(__float_as_uint(b[1])));
}

__device__ __forceinline__ void ldsm_x4(uint32_t addr, float d[4]) {
    uint32_t r0, r1, r2, r3;
    asm volatile("ldmatrix.sync.aligned.m8n8.x4.shared.b16 {%0,%1,%2,%3}, [%4];"
                 : "=r"(r0), "=r"(r1), "=r"(r2), "=r"(r3) : "r"(addr));
    d[0] = __uint_as_float(r0); d[1] = __uint_as_float(r1);
    d[2] = __uint_as_float(r2); d[3] = __uint_as_float(r3);
}

__device__ __forceinline__ uint32_t smem_u32(const void* p) {
    return (uint32_t)__cvta_generic_to_shared(p);
}

__device__ __forceinline__ void cp_async16(uint32_t dst, const void* src) {
    asm volatile("cp.async.cg.shared.global [%0], [%1], 16;"
                 :: "r"(dst), "l"(src) : "memory");
}
__device__ __forceinline__ void cp_commit() {
    asm volatile("cp.async.commit_group;" ::: "memory");
}
__device__ __forceinline__ void cp_wait1() {
    asm volatile("cp.async.wait_group 1;" ::: "memory");
}

// ---------------- prepass: tf32-round operands + rpb expand (one kernel) ----
constexpr int CVT_N0 = MROWS * DIMC / 4;          // x       -> g_xc
constexpr int CVT_N1 = 3 * DIMC * DIMC / 4;       // qkv_w   -> g_wc
constexpr int CVT_N2 = DIMC * DIMC / 4;           // proj_w  -> g_pwc
constexpr int CVT_N3 = NTOK * NTOK;               // rel_idx -> g_rpb
constexpr int CVT_TOT = CVT_N0 + CVT_N1 + CVT_N2 + CVT_N3;
__global__ void prepass_k(const float* __restrict__ x,
                          const float* __restrict__ qw,
                          const float* __restrict__ pw,
                          const int*   __restrict__ rel_idx,
                          const float* __restrict__ table)
{
    int i = blockIdx.x * 256 + threadIdx.x;
    if (i < CVT_N0) {
        float4 v = ((const float4*)x)[i];
        ((float4*)g_xc)[i] = make_float4(f2tf32(v.x), f2tf32(v.y), f2tf32(v.z), f2tf32(v.w));
        return;
    }
    if ((i -= CVT_N0) < CVT_N1) {
        float4 v = ((const float4*)qw)[i];
        ((float4*)g_wc)[i] = make_float4(f2tf32(v.x), f2tf32(v.y), f2tf32(v.z), f2tf32(v.w));
        return;
    }
    if ((i -= CVT_N1) < CVT_N2) {
        float4 v = ((const float4*)pw)[i];
        ((float4*)g_pwc)[i] = make_float4(f2tf32(v.x), f2tf32(v.y), f2tf32(v.z), f2tf32(v.w));
        return;
    }
    if ((i -= CVT_N2) < CVT_N3) {
        int rel = rel_idx[i];
        #pragma unroll
        for (int h = 0; h < NH; h++)
            g_rpb[h * NTOK * NTOK + i] = table[rel * NH + h];
    }
}

// ---------------- TF32 GEMM: 128x128 block, GBK=16, cp.async 3-stage --------
// MODE 0: QKV  [25216,2304] = g_xc @ g_wc^T (+bias, scale, scatter q/k/v)
// MODE 3: proj [25216,768]  = g_o  @ g_pwc^T (+bias)
constexpr int GBM = 128, GBN = 128, GBK = 16, GLD = 20, NSTG = 3;
constexpr int GEMM_SMEM = NSTG * (GBM + GBN) * GLD * 4;   // 61440 B

template<int MODE>
__global__ void __launch_bounds__(128, 2) gemm_tc(const float* __restrict__ P1,
                                                  const float* __restrict__ P2,
                                                  float* __restrict__ C_)
{
    constexpr int Kdim = DIMC;
    constexpr int NKT  = Kdim / GBK;               // 48

    const float* A  = (MODE == 3) ? (const float*)g_o : (const float*)g_xc;
    const float* Bm = (MODE == 3) ? (const float*)g_pwc : (const float*)g_wc;

    const int m0  = blockIdx.y * GBM;
    const int n0  = blockIdx.x * GBN;
    const int tid = threadIdx.x;
    const int w    = tid >> 5, lane = tid & 31;
    const int gid  = lane >> 2, tig = lane & 3;
    const int wm   = (w & 1) * 64;
    const int wn   = (w >> 1) * 64;

    extern __shared__ float smg[];
    float* As = smg;
    float* Bs = smg + NSTG * GBM * GLD;

    const int sr = tid >> 2;
    const int sc = (tid & 3) * 4;

    const float* pa = &A [(size_t)(m0 + sr) * Kdim + sc];
    const float* pb = &Bm[(size_t)(n0 + sr) * Kdim + sc];

    float acc[4][8][4] = {};

    const int lt   = lane >> 3;
    const int li   = lane & 7;
    const int a_row = wm + (lt & 1) * 8 + li;
    const int a_col = (lt >> 1) * 4;
    const int b_row = wn + (lt >> 1) * 8 + li;
    const int b_col = (lt & 1) * 4;

    auto STAGE = [&](int kt_idx, int buf) {
        float* ab = As + buf * GBM * GLD;
        float* bb = Bs + buf * GBN * GLD;
        const int kt = kt_idx * GBK;
        #pragma unroll
        for (int r = 0; r < 4; r++) {
            cp_async16(smem_u32(&ab[(sr + r * 32) * GLD + sc]),
                       pa + (size_t)(r * 32) * Kdim + kt);
            cp_async16(smem_u32(&bb[(sr + r * 32) * GLD + sc]),
                       pb + (size_t)(r * 32) * Kdim + kt);
        }
    };
    auto MMA_ALL = [&](int buf) {
        const float* ab = As + buf * GBM * GLD;
        const float* bb = Bs + buf * GBN * GLD;
        #pragma unroll
        for (int kc = 0; kc < 2; kc++) {
            float af[4][4], bf[8][2];
            #pragma unroll
            for (int mt = 0; mt < 4; mt++) {
                uint32_t ad = smem_u32(&ab[(a_row + mt * 16) * GLD + a_col + kc * 8]);
                ldsm_x4(ad, af[mt]);
            }
            #pragma unroll
            for (int p = 0; p < 4; p++) {
                float t4[4];
                uint32_t ad = smem_u32(&bb[(b_row + p * 16) * GLD + b_col + kc * 8]);
                ldsm_x4(ad, t4);
                bf[p*2  ][0] = t4[0]; bf[p*2  ][1] = t4[1];
                bf[p*2+1][0] = t4[2]; bf[p*2+1][1] = t4[3];
            }
            #pragma unroll
            for (int mt = 0; mt < 4; mt++)
                #pragma unroll
                for (int nt = 0; nt < 8; nt++)
                    mma_tf32(acc[mt][nt], af[mt], bf[nt]);
        }
    };

    STAGE(0, 0); cp_commit();
    STAGE(1, 1); cp_commit();
    for (int it = 0; it < NKT; it++) {
        cp_wait1();
        __syncthreads();
        if (it + 2 < NKT) STAGE(it + 2, (it + 2) % NSTG);
        cp_commit();
        MMA_ALL(it % NSTG);
    }

    #pragma unroll
    for (int mt = 0; mt < 4; mt++) {
        #pragma unroll
        for (int nt = 0; nt < 8; nt++) {
            #pragma unroll
            for (int e = 0; e < 4; e++) {
                int gm = m0 + wm + mt * 16 + gid + ((e >> 1) ? 8 : 0);
                int gn = n0 + wn + nt * 8 + tig * 2 + (e & 1);
                float v = acc[mt][nt][e];
                if (MODE == 0) {
                    int b = gm / NTOK, n = gm % NTOK;
                    int s = gn / DIMC, r = gn % DIMC;
                    int h = r / HDIM,  d = r % HDIM;
                    size_t o = ((size_t)(b * NH + h) * NTOK + n) * HDIM + d;
                    if (s == 0)      g_q[o] = (v + P1[r]) * 0.125f;
                    else if (s == 1) g_k[o] = v;
                    else             g_v[o] = v + P2[r];
                } else {
                    C_[(size_t)gm * DIMC + gn] = v + P1[gn];
                }
            }
        }
    }
}

// ---------------- fused attention: 2 CTAs per (b,h), 4 warps each ------------
constexpr int NP        = 208;
constexpr int KS_STRIDE = 68;
constexpr int VT_STRIDE = 212;
constexpr int ATT_SMEM  = (NP * KS_STRIDE + HDIM * VT_STRIDE) * 4;

__global__ void __launch_bounds__(128, 2) attn_fused_k()
{
    const int z    = blockIdx.x >> 1;
    const int half = blockIdx.x & 1;
    const int h = z % NH;
    const int b = z / NH;
    const float* q   = g_q + (size_t)z * NTOK * HDIM;
    const float* kk  = g_k + (size_t)z * NTOK * HDIM;
    const float* vv  = g_v + (size_t)z * NTOK * HDIM;
    const float* rpb = g_rpb + (size_t)h * NTOK * NTOK;

    extern __shared__ float sm[];
    float* ks = sm;
    float* vT = sm + NP * KS_STRIDE;

    const int tid = threadIdx.x;

    for (int idx = tid; idx < NP * 16; idx += 128) {
        int tok = idx >> 4, d4 = (idx & 15) * 4;
        float4 val = make_float4(0.f, 0.f, 0.f, 0.f);
        if (tok < NTOK) val = *(const float4*)&kk[tok * HDIM + d4];
        ks[tok * KS_STRIDE + d4 + 0] = f2tf32(val.x);
        ks[tok * KS_STRIDE + d4 + 1] = f2tf32(val.y);
        ks[tok * KS_STRIDE + d4 + 2] = f2tf32(val.z);
        ks[tok * KS_STRIDE + d4 + 3] = f2tf32(val.w);
    }
    for (int idx = tid; idx < NP * 16; idx += 128) {
        int tok = idx >> 4, d4 = (idx & 15) * 4;
        float4 val = make_float4(0.f, 0.f, 0.f, 0.f);
        if (tok < NTOK) val = *(const float4*)&vv[tok * HDIM + d4];
        vT[(d4 + 0) * VT_STRIDE + tok] = f2tf32(val.x);
        vT[(d4 + 1) * VT_STRIDE + tok] = f2tf32(val.y);
        vT[(d4 + 2) * VT_STRIDE + tok] = f2tf32(val.z);
        vT[(d4 + 3) * VT_STRIDE + tok] = f2tf32(val.w);
    }
    __syncthreads();

    const int w = tid >> 5, lane = tid & 31, gid = lane >> 2, tig = lane & 3;
    const int lt = lane >> 3, li = lane & 7;
    const int bs_row = (lt >> 1) * 8 + li;
    const int bs_col = (lt & 1) * 4;

    for (int r = 0; r < 2; r++) {
        const int t = half + 2 * (w + 4 * r);
        if (t >= 13) break;
        const int m0 = t * 16;
        const int mA = m0 + gid;
        const int mB = m0 + gid + 8;

        float aq[8][4];
        #pragma unroll
        for (int kt = 0; kt < 8; kt++) {
            int c0 = kt * 8 + tig, c1 = c0 + 4;
            aq[kt][0] = (mA < NTOK) ? f2tf32(q[mA * HDIM + c0]) : 0.f;
            aq[kt][1] = (mB < NTOK) ? f2tf32(q[mB * HDIM + c0]) : 0.f;
            aq[kt][2] = (mA < NTOK) ? f2tf32(q[mA * HDIM + c1]) : 0.f;
            aq[kt][3] = (mB < NTOK) ? f2tf32(q[mB * HDIM + c1]) : 0.f;
        }

        float acc[26][4];
        #pragma unroll
        for (int nt = 0; nt < 26; nt++)
            acc[nt][0] = acc[nt][1] = acc[nt][2] = acc[nt][3] = 0.f;
        #pragma unroll
        for (int np = 0; np < 13; np++) {
            #pragma unroll
            for (int kt = 0; kt < 8; kt++) {
                float t4[4];
                uint32_t ad = smem_u32(&ks[(np * 16 + bs_row) * KS_STRIDE + bs_col + kt * 8]);
                ldsm_x4(ad, t4);
                float bk0[2] = { t4[0], t4[1] };
                float bk1[2] = { t4[2], t4[3] };
                mma_tf32(acc[np * 2    ], aq[kt], bk0);
                mma_tf32(acc[np * 2 + 1], aq[kt], bk1);
            }
        }

        const float* rA = rpb + (size_t)min(mA, NTOK - 1) * NTOK;
        const float* rB = rpb + (size_t)min(mB, NTOK - 1) * NTOK;
        float mx0 = -1e30f, mx1 = -1e30f;
        #pragma unroll
        for (int nt = 0; nt < 26; nt++) {
            int c0 = nt * 8 + tig * 2, c1 = c0 + 1;
            acc[nt][0] = (c0 < NTOK) ? acc[nt][0] + rA[c0] : -1e30f;
            acc[nt][1] = (c1 < NTOK) ? acc[nt][1] + rA[c1] : -1e30f;
            acc[nt][2] = (c0 < NTOK) ? acc[nt][2] + rB[c0] : -1e30f;
            acc[nt][3] = (c1 < NTOK) ? acc[nt][3] + rB[c1] : -1e30f;
            mx0 = fmaxf(mx0, fmaxf(acc[nt][0], acc[nt][1]));
            mx1 = fmaxf(mx1, fmaxf(acc[nt][2], acc[nt][3]));
        }
        #pragma unroll
        for (int o = 1; o <= 2; o <<= 1) {
            mx0 = fmaxf(mx0, __shfl_xor_sync(~0u, mx0, o));
            mx1 = fmaxf(mx1, __shfl_xor_sync(~0u, mx1, o));
        }
        float s0 = 0.f, s1 = 0.f;
        #pragma unroll
        for (int nt = 0; nt < 26; nt++) {
            acc[nt][0] = __expf(acc[nt][0] - mx0);
            acc[nt][1] = __expf(acc[nt][1] - mx0);
            acc[nt][2] = __expf(acc[nt][2] - mx1);
            acc[nt][3] = __expf(acc[nt][3] - mx1);
            s0 += acc[nt][0] + acc[nt][1];
            s1 += acc[nt][2] + acc[nt][3];
        }
        #pragma unroll
        for (int o = 1; o <= 2; o <<= 1) {
            s0 += __shfl_xor_sync(~0u, s0, o);
            s1 += __shfl_xor_sync(~0u, s1, o);
        }
        const float i0 = 1.f / s0, i1 = 1.f / s1;
        #pragma unroll
        for (int nt = 0; nt < 26; nt++) {
            acc[nt][0] *= i0; acc[nt][1] *= i0;
            acc[nt][2] *= i1; acc[nt][3] *= i1;
        }

        float acc2[8][4];
        #pragma unroll
        for (int nt = 0; nt < 8; nt++)
            acc2[nt][0] = acc2[nt][1] = acc2[nt][2] = acc2[nt][3] = 0.f;

        const int src0 = (lane & ~3) | (tig >> 1);
        const int src1 = src0 + 2;
        const bool odd = tig & 1;
        #pragma unroll
        for (int kt = 0; kt < 26; kt++) {
            float v00 = __shfl_sync(~0u, acc[kt][0], src0);
            float v01 = __shfl_sync(~0u, acc[kt][1], src0);
            float v02 = __shfl_sync(~0u, acc[kt][2], src0);
            float v03 = __shfl_sync(~0u, acc[kt][3], src0);
            float w00 = __shfl_sync(~0u, acc[kt][0], src1);
            float w01 = __shfl_sync(~0u, acc[kt][1], src1);
            float w02 = __shfl_sync(~0u, acc[kt][2], src1);
            float w03 = __shfl_sync(~0u, acc[kt][3], src1);
            float aP[4];
            aP[0] = f2tf32(odd ? v01 : v00);
            aP[1] = f2tf32(odd ? v03 : v02);
            aP[2] = f2tf32(odd ? w01 : w00);
            aP[3] = f2tf32(odd ? w03 : w02);
            #pragma unroll
            for (int np = 0; np < 4; np++) {
                float t4[4];
                uint32_t ad = smem_u32(&vT[(np * 16 + bs_row) * VT_STRIDE + bs_col + kt * 8]);
                ldsm_x4(ad, t4);
                float bv0[2] = { t4[0], t4[1] };
                float bv1[2] = { t4[2], t4[3] };
                mma_tf32(acc2[np * 2    ], aP, bv0);
                mma_tf32(acc2[np * 2 + 1], aP, bv1);
            }
        }

        #pragma unroll
        for (int nt = 0; nt < 8; nt++) {
            int d0 = nt * 8 + tig * 2;
            if (mA < NTOK) {
                float* o = &g_o[((size_t)(b * NTOK + mA)) * DIMC + h * HDIM + d0];
                o[0] = f2tf32(acc2[nt][0]); o[1] = f2tf32(acc2[nt][1]);
            }
            if (mB < NTOK) {
                float* o = &g_o[((size_t)(b * NTOK + mB)) * DIMC + h * HDIM + d0];
                o[0] = f2tf32(acc2[nt][2]); o[1] = f2tf32(acc2[nt][3]);
            }
        }
    }
}

// ---------------- launch ----------------
extern "C" void kernel_launch(void* const* d_in, const int* in_sizes, int n_in,
                              void* d_out, int out_size)
{
    const float* x = nullptr; const float* qkv_w = nullptr;
    const float* proj_w = nullptr; const float* rpb_table = nullptr;
    const int*   rel_idx = nullptr;
    const float* bias768[3] = {nullptr, nullptr, nullptr};
    int nbias = 0;
    for (int i = 0; i < n_in; i++) {
        switch (in_sizes[i]) {
            case MROWS * DIMC:    x         = (const float*)d_in[i]; break;
            case 3 * DIMC * DIMC: qkv_w     = (const float*)d_in[i]; break;
            case DIMC * DIMC:     proj_w    = (const float*)d_in[i]; break;
            case NTOK * NTOK:     rel_idx   = (const int*)d_in[i];   break;
            case 732 * NH:        rpb_table = (const float*)d_in[i]; break;
            case DIMC:            if (nbias < 3) bias768[nbias++] = (const float*)d_in[i]; break;
            default: break;
        }
    }
    const float* q_bias = bias768[0];
    const float* v_bias = bias768[1];
    const float* proj_b = bias768[2];
    float* out = (float*)d_out;

    cudaFuncSetAttribute(attn_fused_k, cudaFuncAttributeMaxDynamicSharedMemorySize, ATT_SMEM);
    cudaFuncSetAttribute(gemm_tc<0>, cudaFuncAttributeMaxDynamicSharedMemorySize, GEMM_SMEM);
    cudaFuncSetAttribute(gemm_tc<3>, cudaFuncAttributeMaxDynamicSharedMemorySize, GEMM_SMEM);

    // 0) prepass: tf32-round operands + rpb expand (single kernel)
    prepass_k<<<(CVT_TOT + 255) / 256, 256>>>(x, qkv_w, proj_w, rel_idx, rpb_table);

    // 1) QKV projection: grid (2304/128, 25216/128)
    gemm_tc<0><<<dim3(18, 197), 128, GEMM_SMEM>>>(q_bias, v_bias, nullptr);

    // 2) fused attention: 2 CTAs per (b,h)
    attn_fused_k<<<NBH * 2, 128, ATT_SMEM>>>();

    // 3) final projection + bias: grid (768/128, 197)
    gemm_tc<3><<<dim3(6, 197), 128, GEMM_SMEM>>>(proj_b, nullptr, out);
}

// round 16
// speedup vs baseline: 1.5479x; 1.0303x over previous
#include <cuda_runtime.h>
#include <cstdint>

// ---------------- problem constants ----------------
constexpr int NTOK  = 197;
constexpr int DIMC  = 768;
constexpr int NH    = 12;
constexpr int HDIM  = 64;
constexpr int NB    = 128;
constexpr int MROWS = NB * NTOK;    // 25216
constexpr int NBH   = NB * NH;      // 1536

// ---------------- scratch (device globals) ----------------
__device__ float g_q[(size_t)NBH * NTOK * HDIM];   // tf32-rounded at QKV epilogue
__device__ float g_k[(size_t)NBH * NTOK * HDIM];   // tf32-rounded at QKV epilogue
__device__ float g_v[(size_t)NBH * NTOK * HDIM];   // tf32-rounded at QKV epilogue
__device__ float g_o[(size_t)MROWS * DIMC];        // tf32-rounded by attention
__device__ float g_rpb[NH * NTOK * NTOK];
__device__ float g_xc[(size_t)MROWS * DIMC];       // tf32-rounded x
__device__ float g_wc[(size_t)3 * DIMC * DIMC];    // tf32-rounded qkv_w
__device__ float g_pwc[(size_t)DIMC * DIMC];       // tf32-rounded proj_w

// ---------------- helpers ----------------
__device__ __forceinline__ float f2tf32(float x) {
    unsigned u;
    asm("cvt.rna.tf32.f32 %0, %1;" : "=r"(u) : "f"(x));
    return __uint_as_float(u);
}

__device__ __forceinline__ void mma_tf32(float c[4], const float a[4], const float b[2]) {
    asm volatile(
        "mma.sync.aligned.m16n8k8.row.col.f32.tf32.tf32.f32 "
        "{%0,%1,%2,%3}, {%4,%5,%6,%7}, {%8,%9}, {%0,%1,%2,%3};"
        : "+f"(c[0]), "+f"(c[1]), "+f"(c[2]), "+f"(c[3])
        : "r"(__float_as_uint(a[0])), "r"(__float_as_uint(a[1])),
          "r"(__float_as_uint(a[2])), "r"(__float_as_uint(a[3])),
          "r"(__float_as_uint(b[0])), "r"(__float_as_uint(b[1])));
}

__device__ __forceinline__ void ldsm_x4(uint32_t addr, float d[4]) {
    uint32_t r0, r1, r2, r3;
    asm volatile("ldmatrix.sync.aligned.m8n8.x4.shared.b16 {%0,%1,%2,%3}, [%4];"
                 : "=r"(r0), "=r"(r1), "=r"(r2), "=r"(r3) : "r"(addr));
    d[0] = __uint_as_float(r0); d[1] = __uint_as_float(r1);
    d[2] = __uint_as_float(r2); d[3] = __uint_as_float(r3);
}

__device__ __forceinline__ uint32_t smem_u32(const void* p) {
    return (uint32_t)__cvta_generic_to_shared(p);
}

__device__ __forceinline__ void cp_async16(uint32_t dst, const void* src) {
    asm volatile("cp.async.cg.shared.global [%0], [%1], 16;"
                 :: "r"(dst), "l"(src) : "memory");
}
__device__ __forceinline__ void cp_commit() {
    asm volatile("cp.async.commit_group;" ::: "memory");
}
__device__ __forceinline__ void cp_wait1() {
    asm volatile("cp.async.wait_group 1;" ::: "memory");
}
__device__ __forceinline__ void cp_wait0() {
    asm volatile("cp.async.wait_group 0;" ::: "memory");
}

// ---------------- prepass: tf32-round operands + rpb expand (one kernel) ----
constexpr int CVT_N0 = MROWS * DIMC / 4;          // x       -> g_xc
constexpr int CVT_N1 = 3 * DIMC * DIMC / 4;       // qkv_w   -> g_wc
constexpr int CVT_N2 = DIMC * DIMC / 4;           // proj_w  -> g_pwc
constexpr int CVT_N3 = NTOK * NTOK;               // rel_idx -> g_rpb
constexpr int CVT_TOT = CVT_N0 + CVT_N1 + CVT_N2 + CVT_N3;
__global__ void prepass_k(const float* __restrict__ x,
                          const float* __restrict__ qw,
                          const float* __restrict__ pw,
                          const int*   __restrict__ rel_idx,
                          const float* __restrict__ table)
{
    int i = blockIdx.x * 256 + threadIdx.x;
    if (i < CVT_N0) {
        float4 v = ((const float4*)x)[i];
        ((float4*)g_xc)[i] = make_float4(f2tf32(v.x), f2tf32(v.y), f2tf32(v.z), f2tf32(v.w));
        return;
    }
    if ((i -= CVT_N0) < CVT_N1) {
        float4 v = ((const float4*)qw)[i];
        ((float4*)g_wc)[i] = make_float4(f2tf32(v.x), f2tf32(v.y), f2tf32(v.z), f2tf32(v.w));
        return;
    }
    if ((i -= CVT_N1) < CVT_N2) {
        float4 v = ((const float4*)pw)[i];
        ((float4*)g_pwc)[i] = make_float4(f2tf32(v.x), f2tf32(v.y), f2tf32(v.z), f2tf32(v.w));
        return;
    }
    if ((i -= CVT_N2) < CVT_N3) {
        int rel = rel_idx[i];
        #pragma unroll
        for (int h = 0; h < NH; h++)
            g_rpb[h * NTOK * NTOK + i] = table[rel * NH + h];
    }
}

// ---------------- TF32 GEMM: 128x128 block, GBK=16, cp.async 3-stage --------
// MODE 0: QKV  [25216,2304] = g_xc @ g_wc^T (+bias, scale, scatter q/k/v tf32)
// MODE 3: proj [25216,768]  = g_o  @ g_pwc^T (+bias)
constexpr int GBM = 128, GBN = 128, GBK = 16, GLD = 20, NSTG = 3;
constexpr int GEMM_SMEM = NSTG * (GBM + GBN) * GLD * 4;   // 61440 B

template<int MODE>
__global__ void __launch_bounds__(128, 2) gemm_tc(const float* __restrict__ P1,
                                                  const float* __restrict__ P2,
                                                  float* __restrict__ C_)
{
    constexpr int Kdim = DIMC;
    constexpr int NKT  = Kdim / GBK;               // 48

    const float* A  = (MODE == 3) ? (const float*)g_o : (const float*)g_xc;
    const float* Bm = (MODE == 3) ? (const float*)g_pwc : (const float*)g_wc;

    const int m0  = blockIdx.y * GBM;
    const int n0  = blockIdx.x * GBN;
    const int tid = threadIdx.x;
    const int w    = tid >> 5, lane = tid & 31;
    const int gid  = lane >> 2, tig = lane & 3;
    const int wm   = (w & 1) * 64;
    const int wn   = (w >> 1) * 64;

    extern __shared__ float smg[];
    float* As = smg;
    float* Bs = smg + NSTG * GBM * GLD;

    const int sr = tid >> 2;
    const int sc = (tid & 3) * 4;

    const float* pa = &A [(size_t)(m0 + sr) * Kdim + sc];
    const float* pb = &Bm[(size_t)(n0 + sr) * Kdim + sc];

    float acc[4][8][4] = {};

    const int lt   = lane >> 3;
    const int li   = lane & 7;
    const int a_row = wm + (lt & 1) * 8 + li;
    const int a_col = (lt >> 1) * 4;
    const int b_row = wn + (lt >> 1) * 8 + li;
    const int b_col = (lt & 1) * 4;

    auto STAGE = [&](int kt_idx, int buf) {
        float* ab = As + buf * GBM * GLD;
        float* bb = Bs + buf * GBN * GLD;
        const int kt = kt_idx * GBK;
        #pragma unroll
        for (int r = 0; r < 4; r++) {
            cp_async16(smem_u32(&ab[(sr + r * 32) * GLD + sc]),
                       pa + (size_t)(r * 32) * Kdim + kt);
            cp_async16(smem_u32(&bb[(sr + r * 32) * GLD + sc]),
                       pb + (size_t)(r * 32) * Kdim + kt);
        }
    };
    auto MMA_ALL = [&](int buf) {
        const float* ab = As + buf * GBM * GLD;
        const float* bb = Bs + buf * GBN * GLD;
        #pragma unroll
        for (int kc = 0; kc < 2; kc++) {
            float af[4][4], bf[8][2];
            #pragma unroll
            for (int mt = 0; mt < 4; mt++) {
                uint32_t ad = smem_u32(&ab[(a_row + mt * 16) * GLD + a_col + kc * 8]);
                ldsm_x4(ad, af[mt]);
            }
            #pragma unroll
            for (int p = 0; p < 4; p++) {
                float t4[4];
                uint32_t ad = smem_u32(&bb[(b_row + p * 16) * GLD + b_col + kc * 8]);
                ldsm_x4(ad, t4);
                bf[p*2  ][0] = t4[0]; bf[p*2  ][1] = t4[1];
                bf[p*2+1][0] = t4[2]; bf[p*2+1][1] = t4[3];
            }
            #pragma unroll
            for (int mt = 0; mt < 4; mt++)
                #pragma unroll
                for (int nt = 0; nt < 8; nt++)
                    mma_tf32(acc[mt][nt], af[mt], bf[nt]);
        }
    };

    STAGE(0, 0); cp_commit();
    STAGE(1, 1); cp_commit();
    for (int it = 0; it < NKT; it++) {
        cp_wait1();
        __syncthreads();
        if (it + 2 < NKT) STAGE(it + 2, (it + 2) % NSTG);
        cp_commit();
        MMA_ALL(it % NSTG);
    }

    #pragma unroll
    for (int mt = 0; mt < 4; mt++) {
        #pragma unroll
        for (int nt = 0; nt < 8; nt++) {
            #pragma unroll
            for (int e = 0; e < 4; e++) {
                int gm = m0 + wm + mt * 16 + gid + ((e >> 1) ? 8 : 0);
                int gn = n0 + wn + nt * 8 + tig * 2 + (e & 1);
                float v = acc[mt][nt][e];
                if (MODE == 0) {
                    int b = gm / NTOK, n = gm % NTOK;
                    int s = gn / DIMC, r = gn % DIMC;
                    int h = r / HDIM,  d = r % HDIM;
                    size_t o = ((size_t)(b * NH + h) * NTOK + n) * HDIM + d;
                    // tf32-rounded at write: identical to rounding at attention load
                    if (s == 0)      g_q[o] = f2tf32((v + P1[r]) * 0.125f);
                    else if (s == 1) g_k[o] = f2tf32(v);
                    else             g_v[o] = f2tf32(v + P2[r]);
                } else {
                    C_[(size_t)gm * DIMC + gn] = v + P1[gn];
                }
            }
        }
    }
}

// ---------------- fused attention: 2 CTAs per (b,h), 4 warps each ------------
// q/k/v arrive pre-rounded; ks staged via cp.async (pure copy), vT via LDG/STS.
constexpr int NP        = 208;
constexpr int KS_STRIDE = 68;
constexpr int VT_STRIDE = 212;
constexpr int ATT_SMEM  = (NP * KS_STRIDE + HDIM * VT_STRIDE) * 4;

__global__ void __launch_bounds__(128, 2) attn_fused_k()
{
    const int z    = blockIdx.x >> 1;
    const int half = blockIdx.x & 1;
    const int h = z % NH;
    const int b = z / NH;
    const float* q   = g_q + (size_t)z * NTOK * HDIM;
    const float* kk  = g_k + (size_t)z * NTOK * HDIM;
    const float* vv  = g_v + (size_t)z * NTOK * HDIM;
    const float* rpb = g_rpb + (size_t)h * NTOK * NTOK;

    extern __shared__ float sm[];
    float* ks = sm;
    float* vT = sm + NP * KS_STRIDE;
    const uint32_t ks_base = smem_u32(ks);

    const int tid = threadIdx.x;

    // ---- stage K via cp.async (pure copy; zero-fill tail rows) ----
    for (int idx = tid; idx < NP * 16; idx += 128) {
        int tok = idx >> 4, d4 = (idx & 15) * 4;
        uint32_t dst = ks_base + (tok * KS_STRIDE + d4) * 4;
        if (tok < NTOK) {
            cp_async16(dst, &kk[tok * HDIM + d4]);
        } else {
            asm volatile("st.shared.v4.b32 [%0], {%1,%1,%1,%1};"
                         :: "r"(dst), "r"(0u) : "memory");
        }
    }
    cp_commit();
    // ---- stage V transposed (overlaps with K cp.async in flight) ----
    for (int idx = tid; idx < NP * 16; idx += 128) {
        int tok = idx >> 4, d4 = (idx & 15) * 4;
        float4 val = make_float4(0.f, 0.f, 0.f, 0.f);
        if (tok < NTOK) val = *(const float4*)&vv[tok * HDIM + d4];
        vT[(d4 + 0) * VT_STRIDE + tok] = val.x;
        vT[(d4 + 1) * VT_STRIDE + tok] = val.y;
        vT[(d4 + 2) * VT_STRIDE + tok] = val.z;
        vT[(d4 + 3) * VT_STRIDE + tok] = val.w;
    }
    cp_wait0();
    __syncthreads();

    const int w = tid >> 5, lane = tid & 31, gid = lane >> 2, tig = lane & 3;
    const int lt = lane >> 3, li = lane & 7;
    const int bs_row = (lt >> 1) * 8 + li;
    const int bs_col = (lt & 1) * 4;

    for (int r = 0; r < 2; r++) {
        const int t = half + 2 * (w + 4 * r);
        if (t >= 13) break;
        const int m0 = t * 16;
        const int mA = m0 + gid;
        const int mB = m0 + gid + 8;

        float aq[8][4];
        #pragma unroll
        for (int kt = 0; kt < 8; kt++) {
            int c0 = kt * 8 + tig, c1 = c0 + 4;
            aq[kt][0] = (mA < NTOK) ? q[mA * HDIM + c0] : 0.f;
            aq[kt][1] = (mB < NTOK) ? q[mB * HDIM + c0] : 0.f;
            aq[kt][2] = (mA < NTOK) ? q[mA * HDIM + c1] : 0.f;
            aq[kt][3] = (mB < NTOK) ? q[mB * HDIM + c1] : 0.f;
        }

        float acc[26][4];
        #pragma unroll
        for (int nt = 0; nt < 26; nt++)
            acc[nt][0] = acc[nt][1] = acc[nt][2] = acc[nt][3] = 0.f;
        #pragma unroll
        for (int np = 0; np < 13; np++) {
            #pragma unroll
            for (int kt = 0; kt < 8; kt++) {
                float t4[4];
                uint32_t ad = smem_u32(&ks[(np * 16 + bs_row) * KS_STRIDE + bs_col + kt * 8]);
                ldsm_x4(ad, t4);
                float bk0[2] = { t4[0], t4[1] };
                float bk1[2] = { t4[2], t4[3] };
                mma_tf32(acc[np * 2    ], aq[kt], bk0);
                mma_tf32(acc[np * 2 + 1], aq[kt], bk1);
            }
        }

        const float* rA = rpb + (size_t)min(mA, NTOK - 1) * NTOK;
        const float* rB = rpb + (size_t)min(mB, NTOK - 1) * NTOK;
        float mx0 = -1e30f, mx1 = -1e30f;
        #pragma unroll
        for (int nt = 0; nt < 26; nt++) {
            int c0 = nt * 8 + tig * 2, c1 = c0 + 1;
            acc[nt][0] = (c0 < NTOK) ? acc[nt][0] + rA[c0] : -1e30f;
            acc[nt][1] = (c1 < NTOK) ? acc[nt][1] + rA[c1] : -1e30f;
            acc[nt][2] = (c0 < NTOK) ? acc[nt][2] + rB[c0] : -1e30f;
            acc[nt][3] = (c1 < NTOK) ? acc[nt][3] + rB[c1] : -1e30f;
            mx0 = fmaxf(mx0, fmaxf(acc[nt][0], acc[nt][1]));
            mx1 = fmaxf(mx1, fmaxf(acc[nt][2], acc[nt][3]));
        }
        #pragma unroll
        for (int o = 1; o <= 2; o <<= 1) {
            mx0 = fmaxf(mx0, __shfl_xor_sync(~0u, mx0, o));
            mx1 = fmaxf(mx1, __shfl_xor_sync(~0u, mx1, o));
        }
        float s0 = 0.f, s1 = 0.f;
        #pragma unroll
        for (int nt = 0; nt < 26; nt++) {
            acc[nt][0] = __expf(acc[nt][0] - mx0);
            acc[nt][1] = __expf(acc[nt][1] - mx0);
            acc[nt][2] = __expf(acc[nt][2] - mx1);
            acc[nt][3] = __expf(acc[nt][3] - mx1);
            s0 += acc[nt][0] + acc[nt][1];
            s1 += acc[nt][2] + acc[nt][3];
        }
        #pragma unroll
        for (int o = 1; o <= 2; o <<= 1) {
            s0 += __shfl_xor_sync(~0u, s0, o);
            s1 += __shfl_xor_sync(~0u, s1, o);
        }
        const float i0 = 1.f / s0, i1 = 1.f / s1;
        #pragma unroll
        for (int nt = 0; nt < 26; nt++) {
            acc[nt][0] *= i0; acc[nt][1] *= i0;
            acc[nt][2] *= i1; acc[nt][3] *= i1;
        }

        float acc2[8][4];
        #pragma unroll
        for (int nt = 0; nt < 8; nt++)
            acc2[nt][0] = acc2[nt][1] = acc2[nt][2] = acc2[nt][3] = 0.f;

        const int src0 = (lane & ~3) | (tig >> 1);
        const int src1 = src0 + 2;
        const bool odd = tig & 1;
        #pragma unroll
        for (int kt = 0; kt < 26; kt++) {
            float v00 = __shfl_sync(~0u, acc[kt][0], src0);
            float v01 = __shfl_sync(~0u, acc[kt][1], src0);
            float v02 = __shfl_sync(~0u, acc[kt][2], src0);
            float v03 = __shfl_sync(~0u, acc[kt][3], src0);
            float w00 = __shfl_sync(~0u, acc[kt][0], src1);
            float w01 = __shfl_sync(~0u, acc[kt][1], src1);
            float w02 = __shfl_sync(~0u, acc[kt][2], src1);
            float w03 = __shfl_sync(~0u, acc[kt][3], src1);
            float aP[4];
            aP[0] = f2tf32(odd ? v01 : v00);
            aP[1] = f2tf32(odd ? v03 : v02);
            aP[2] = f2tf32(odd ? w01 : w00);
            aP[3] = f2tf32(odd ? w03 : w02);
            #pragma unroll
            for (int np = 0; np < 4; np++) {
                float t4[4];
                uint32_t ad = smem_u32(&vT[(np * 16 + bs_row) * VT_STRIDE + bs_col + kt * 8]);
                ldsm_x4(ad, t4);
                float bv0[2] = { t4[0], t4[1] };
                float bv1[2] = { t4[2], t4[3] };
                mma_tf32(acc2[np * 2    ], aP, bv0);
                mma_tf32(acc2[np * 2 + 1], aP, bv1);
            }
        }

        #pragma unroll
        for (int nt = 0; nt < 8; nt++) {
            int d0 = nt * 8 + tig * 2;
            if (mA < NTOK) {
                float* o = &g_o[((size_t)(b * NTOK + mA)) * DIMC + h * HDIM + d0];
                o[0] = f2tf32(acc2[nt][0]); o[1] = f2tf32(acc2[nt][1]);
            }
            if (mB < NTOK) {
                float* o = &g_o[((size_t)(b * NTOK + mB)) * DIMC + h * HDIM + d0];
                o[0] = f2tf32(acc2[nt][2]); o[1] = f2tf32(acc2[nt][3]);
            }
        }
    }
}

// ---------------- launch ----------------
extern "C" void kernel_launch(void* const* d_in, const int* in_sizes, int n_in,
                              void* d_out, int out_size)
{
    const float* x = nullptr; const float* qkv_w = nullptr;
    const float* proj_w = nullptr; const float* rpb_table = nullptr;
    const int*   rel_idx = nullptr;
    const float* bias768[3] = {nullptr, nullptr, nullptr};
    int nbias = 0;
    for (int i = 0; i < n_in; i++) {
        switch (in_sizes[i]) {
            case MROWS * DIMC:    x         = (const float*)d_in[i]; break;
            case 3 * DIMC * DIMC: qkv_w     = (const float*)d_in[i]; break;
            case DIMC * DIMC:     proj_w    = (const float*)d_in[i]; break;
            case NTOK * NTOK:     rel_idx   = (const int*)d_in[i];   break;
            case 732 * NH:        rpb_table = (const float*)d_in[i]; break;
            case DIMC:            if (nbias < 3) bias768[nbias++] = (const float*)d_in[i]; break;
            default: break;
        }
    }
    const float* q_bias = bias768[0];
    const float* v_bias = bias768[1];
    const float* proj_b = bias768[2];
    float* out = (float*)d_out;

    cudaFuncSetAttribute(attn_fused_k, cudaFuncAttributeMaxDynamicSharedMemorySize, ATT_SMEM);
    cudaFuncSetAttribute(gemm_tc<0>, cudaFuncAttributeMaxDynamicSharedMemorySize, GEMM_SMEM);
    cudaFuncSetAttribute(gemm_tc<3>, cudaFuncAttributeMaxDynamicSharedMemorySize, GEMM_SMEM);

    // 0) prepass: tf32-round operands + rpb expand (single kernel)
    prepass_k<<<(CVT_TOT + 255) / 256, 256>>>(x, qkv_w, proj_w, rel_idx, rpb_table);

    // 1) QKV projection: grid (2304/128, 25216/128)
    gemm_tc<0><<<dim3(18, 197), 128, GEMM_SMEM>>>(q_bias, v_bias, nullptr);

    // 2) fused attention: 2 CTAs per (b,h)
    attn_fused_k<<<NBH * 2, 128, ATT_SMEM>>>();

    // 3) final projection + bias: grid (768/128, 197)
    gemm_tc<3><<<dim3(6, 197), 128, GEMM_SMEM>>>(proj_b, nullptr, out);
}